// round 1
// baseline (speedup 1.0000x reference)
#include <cuda_runtime.h>

// HamiltonianEvolution: out = reshape( q_left_n ⊗ (gate*x) ⊗ conj(q_right_n) )
// The FFT/IFFT pair in the reference is an identity because the spectral gate
// is constant along the FFT (time) axis:  ifft(fft(x)*g) == g*x  when g does
// not depend on frequency. So the whole op collapses to a per-channel 4x4
// linear map applied to every (b,t) position.

#define QD 256   // quat_dim
#define NG 64    // channel groups of 4 (float4 lanes)

// Composite matrices: M[(r*4+c)*NG + grp] holds entry (r,c) for 4 channels.
__device__ float4 g_M[16 * NG];

__global__ void precompute_kernel(const float* __restrict__ q_left,
                                  const float* __restrict__ q_right,
                                  const float* __restrict__ gate) {
    int j = threadIdx.x;
    if (j >= QD) return;

    float lw = q_left[0 * QD + j], lx = q_left[1 * QD + j];
    float ly = q_left[2 * QD + j], lz = q_left[3 * QD + j];
    float rw = q_right[0 * QD + j], rx = q_right[1 * QD + j];
    float ry = q_right[2 * QD + j], rz = q_right[3 * QD + j];

    // normalize (matches reference: q / sqrt(sum(q*q) + 1e-8))
    float ln = rsqrtf(lw * lw + lx * lx + ly * ly + lz * lz + 1e-8f);
    lw *= ln; lx *= ln; ly *= ln; lz *= ln;
    float rn = rsqrtf(rw * rw + rx * rx + ry * ry + rz * rz + 1e-8f);
    // fold conjugation of q_right into the normalized components
    rw = rw * rn; rx = -rx * rn; ry = -ry * rn; rz = -rz * rn;

    float g = gate[j];

    // R: matrix of p -> p ⊗ rc   (rc = conjugated normalized q_right)
    float R[4][4] = {
        { rw, -rx, -ry, -rz},
        { rx,  rw,  rz, -ry},
        { ry, -rz,  rw,  rx},
        { rz,  ry, -rx,  rw}
    };
    // L: matrix of p -> l ⊗ p   (l = normalized q_left)
    float L[4][4] = {
        { lw, -lx, -ly, -lz},
        { lx,  lw, -lz,  ly},
        { ly,  lz,  lw, -lx},
        { lz, -ly,  lx,  lw}
    };

    float* Mf = reinterpret_cast<float*>(g_M);
    #pragma unroll
    for (int r = 0; r < 4; r++) {
        #pragma unroll
        for (int c = 0; c < 4; c++) {
            float acc = 0.0f;
            #pragma unroll
            for (int k = 0; k < 4; k++) acc += L[r][k] * R[k][c];
            Mf[(r * 4 + c) * QD + j] = g * acc;
        }
    }
}

__global__ __launch_bounds__(256)
void apply_kernel(const float4* __restrict__ x, float4* __restrict__ out, int nrows) {
    const int grp = threadIdx.x & 63;   // channel group (4 channels)
    const int sub = threadIdx.x >> 6;   // row within block tile (0..3)

    // Coefficients: 16 float4 = 64 registers, reused across all rows handled
    // by this thread. g_M is 16 KB and L2-resident after the first wave.
    float4 M[16];
    #pragma unroll
    for (int i = 0; i < 16; i++) M[i] = g_M[i * NG + grp];

    const int rowStride = gridDim.x * 4;
    for (int row = blockIdx.x * 4 + sub; row < nrows; row += rowStride) {
        const float4* xr = x + (size_t)row * 256;  // row = 1024 floats = 256 float4
        float4 iw = xr[0 * 64 + grp];
        float4 ix = xr[1 * 64 + grp];
        float4 iy = xr[2 * 64 + grp];
        float4 iz = xr[3 * 64 + grp];

        float4 o[4];
        #pragma unroll
        for (int r = 0; r < 4; r++) {
            const float4 m0 = M[r * 4 + 0];
            const float4 m1 = M[r * 4 + 1];
            const float4 m2 = M[r * 4 + 2];
            const float4 m3 = M[r * 4 + 3];
            o[r].x = fmaf(m0.x, iw.x, fmaf(m1.x, ix.x, fmaf(m2.x, iy.x, m3.x * iz.x)));
            o[r].y = fmaf(m0.y, iw.y, fmaf(m1.y, ix.y, fmaf(m2.y, iy.y, m3.y * iz.y)));
            o[r].z = fmaf(m0.z, iw.z, fmaf(m1.z, ix.z, fmaf(m2.z, iy.z, m3.z * iz.z)));
            o[r].w = fmaf(m0.w, iw.w, fmaf(m1.w, ix.w, fmaf(m2.w, iy.w, m3.w * iz.w)));
        }

        float4* orow = out + (size_t)row * 256;
        orow[0 * 64 + grp] = o[0];
        orow[1 * 64 + grp] = o[1];
        orow[2 * 64 + grp] = o[2];
        orow[3 * 64 + grp] = o[3];
    }
}

extern "C" void kernel_launch(void* const* d_in, const int* in_sizes, int n_in,
                              void* d_out, int out_size) {
    const float* x     = (const float*)d_in[0];   // (B, T, 1024) = 16,777,216 floats
    const float* q_l   = (const float*)d_in[1];   // (4, 256)
    const float* q_r   = (const float*)d_in[2];   // (4, 256)
    const float* gate  = (const float*)d_in[3];   // (1,1,1,256)

    const int nrows = in_sizes[0] / 1024;         // B*T = 16384

    precompute_kernel<<<1, 256>>>(q_l, q_r, gate);
    apply_kernel<<<1024, 256>>>((const float4*)x, (float4*)d_out, nrows);
}

// round 3
// speedup vs baseline: 1.3653x; 1.3653x over previous
#include <cuda_runtime.h>

// HamiltonianEvolution: out = q_left_n ⊗ (gate*x) ⊗ conj(q_right_n).
// The FFT/IFFT pair in the reference is an identity (gate is constant along
// the FFT axis), so the op collapses to a per-channel 4x4 linear map.
// Single fused kernel: every block rebuilds the 256 composite matrices into
// shared memory (cheap, L2-resident inputs), then streams 8 rows.

#define QD 256   // quat_dim
#define NG 64    // channel groups of 4 (float4 lanes)
#define ROWS_PER_BLOCK 8

__global__ __launch_bounds__(256)
void fused_kernel(const float* __restrict__ q_left,
                  const float* __restrict__ q_right,
                  const float* __restrict__ gate,
                  const float4* __restrict__ x,
                  float4* __restrict__ out,
                  int nrows) {
    // sM[i][g] = float4 of matrix entry i=(r*4+c) for channel group g
    __shared__ float4 sM[16][NG];

    const int tid = threadIdx.x;

    // ---- per-block matrix build: thread tid owns channel j = tid ----
    {
        const int j = tid;
        float lw = q_left[0 * QD + j], lx = q_left[1 * QD + j];
        float ly = q_left[2 * QD + j], lz = q_left[3 * QD + j];
        float rw = q_right[0 * QD + j], rx = q_right[1 * QD + j];
        float ry = q_right[2 * QD + j], rz = q_right[3 * QD + j];

        float ln = rsqrtf(lw * lw + lx * lx + ly * ly + lz * lz + 1e-8f);
        lw *= ln; lx *= ln; ly *= ln; lz *= ln;
        float rn = rsqrtf(rw * rw + rx * rx + ry * ry + rz * rz + 1e-8f);
        rw = rw * rn; rx = -rx * rn; ry = -ry * rn; rz = -rz * rn;

        const float g = gate[j];

        // R: p -> p ⊗ rc (rc = conjugated normalized q_right)
        const float R[4][4] = {
            { rw, -rx, -ry, -rz},
            { rx,  rw,  rz, -ry},
            { ry, -rz,  rw,  rx},
            { rz,  ry, -rx,  rw}
        };
        // L: p -> l ⊗ p (l = normalized q_left)
        const float L[4][4] = {
            { lw, -lx, -ly, -lz},
            { lx,  lw, -lz,  ly},
            { ly,  lz,  lw, -lx},
            { lz, -ly,  lx,  lw}
        };

        float* s = reinterpret_cast<float*>(sM);
        #pragma unroll
        for (int r = 0; r < 4; r++) {
            #pragma unroll
            for (int c = 0; c < 4; c++) {
                float acc = 0.0f;
                #pragma unroll
                for (int k = 0; k < 4; k++) acc += L[r][k] * R[k][c];
                s[(r * 4 + c) * QD + j] = g * acc;   // conflict-free write
            }
        }
    }
    __syncthreads();

    // ---- streaming: 2 rows per thread, loads front-batched (MLP=8) ----
    const int grp = tid & 63;   // channel group
    const int sub = tid >> 6;   // 0..3

    const int row0 = blockIdx.x * ROWS_PER_BLOCK + sub;
    const int row1 = row0 + 4;

    const float4* xr0 = x + (size_t)row0 * 256;
    const float4* xr1 = x + (size_t)row1 * 256;

    float4 a0, b0, c0, d0, a1, b1, c1, d1;
    const bool v0 = row0 < nrows;
    const bool v1 = row1 < nrows;
    if (v0) {
        a0 = xr0[0 * 64 + grp];
        b0 = xr0[1 * 64 + grp];
        c0 = xr0[2 * 64 + grp];
        d0 = xr0[3 * 64 + grp];
    }
    if (v1) {
        a1 = xr1[0 * 64 + grp];
        b1 = xr1[1 * 64 + grp];
        c1 = xr1[2 * 64 + grp];
        d1 = xr1[3 * 64 + grp];
    }

    float4* or0 = out + (size_t)row0 * 256;
    float4* or1 = out + (size_t)row1 * 256;

    #pragma unroll
    for (int r = 0; r < 4; r++) {
        const float4 m0 = sM[r * 4 + 0][grp];
        const float4 m1 = sM[r * 4 + 1][grp];
        const float4 m2 = sM[r * 4 + 2][grp];
        const float4 m3 = sM[r * 4 + 3][grp];

        if (v0) {
            float4 o;
            o.x = fmaf(m0.x, a0.x, fmaf(m1.x, b0.x, fmaf(m2.x, c0.x, m3.x * d0.x)));
            o.y = fmaf(m0.y, a0.y, fmaf(m1.y, b0.y, fmaf(m2.y, c0.y, m3.y * d0.y)));
            o.z = fmaf(m0.z, a0.z, fmaf(m1.z, b0.z, fmaf(m2.z, c0.z, m3.z * d0.z)));
            o.w = fmaf(m0.w, a0.w, fmaf(m1.w, b0.w, fmaf(m2.w, c0.w, m3.w * d0.w)));
            or0[r * 64 + grp] = o;
        }
        if (v1) {
            float4 o;
            o.x = fmaf(m0.x, a1.x, fmaf(m1.x, b1.x, fmaf(m2.x, c1.x, m3.x * d1.x)));
            o.y = fmaf(m0.y, a1.y, fmaf(m1.y, b1.y, fmaf(m2.y, c1.y, m3.y * d1.y)));
            o.z = fmaf(m0.z, a1.z, fmaf(m1.z, b1.z, fmaf(m2.z, c1.z, m3.z * d1.z)));
            o.w = fmaf(m0.w, a1.w, fmaf(m1.w, b1.w, fmaf(m2.w, c1.w, m3.w * d1.w)));
            or1[r * 64 + grp] = o;
        }
    }
}

extern "C" void kernel_launch(void* const* d_in, const int* in_sizes, int n_in,
                              void* d_out, int out_size) {
    const float* x    = (const float*)d_in[0];   // (B, T, 1024)
    const float* q_l  = (const float*)d_in[1];   // (4, 256)
    const float* q_r  = (const float*)d_in[2];   // (4, 256)
    const float* gate = (const float*)d_in[3];   // (1,1,1,256)

    const int nrows = in_sizes[0] / 1024;        // B*T
    const int grid = (nrows + ROWS_PER_BLOCK - 1) / ROWS_PER_BLOCK;

    fused_kernel<<<grid, 256>>>(q_l, q_r, gate,
                                reinterpret_cast<const float4*>(x),
                                reinterpret_cast<float4*>(d_out),
                                nrows);
}